// round 16
// baseline (speedup 1.0000x reference)
#include <cuda_runtime.h>
#include <cuda_fp16.h>
#include <cstdint>

#define BB   512
#define NN   256
#define NVT  32
#define HS   128
#define G3   384
#define NZ   64

// ---------- device globals (no allocation allowed) ----------
// B fragments (fp16): [tile(64)][lane(32)] x uint4 = 32 KB
// tile 2p = X (r,z of h in [4p,4p+4)), tile 2p+1 = Y (n,tbl)
__device__ uint4 g_Bf4[2048];
// gi packed: [h(128)][t(32)] x 4 fp16 {gi_r, gi_z, gi_n, bhn_h} = 32 KB
__device__ uint4 g_gi4[2048];
// A fragments per batch (fp16): [mt(16)][k(2)][lane(32)][reg(4)] = 16 KB/batch
__device__ uint4 g_Af4[(size_t)BB * 1024];

__device__ __forceinline__ float tanh_fast(float x) {
    float y;
    asm("tanh.approx.f32 %0, %1;" : "=f"(y) : "f"(x));
    return y;
}
__device__ __forceinline__ float sigmoid_fast(float x) {
    return fmaf(tanh_fast(0.5f * x), 0.5f, 0.5f);
}
__device__ __forceinline__ void mma_fp16(float* c, const uint32_t* a,
                                         uint32_t b0, uint32_t b1) {
    asm volatile(
        "mma.sync.aligned.m16n8k16.row.col.f32.f16.f16.f32 "
        "{%0,%1,%2,%3}, {%4,%5,%6,%7}, {%8,%9}, {%0,%1,%2,%3};"
        : "+f"(c[0]), "+f"(c[1]), "+f"(c[2]), "+f"(c[3])
        : "r"(a[0]), "r"(a[1]), "r"(a[2]), "r"(a[3]), "r"(b0), "r"(b1));
}

// ---------- fused kernel: blocks [0,512) histogram, [512,544) tables --------
__global__ __launch_bounds__(256, 6)
void dvae_hist_tables_kernel(const int* __restrict__ node_types,
                             const int* __restrict__ adj,
                             const float* __restrict__ W_ih,
                             const float* __restrict__ W_hh,
                             const float* __restrict__ b_ih,
                             const float* __restrict__ b_hh,
                             const float* __restrict__ Wg,
                             const float* __restrict__ bg,
                             const float* __restrict__ Wm) {
    // [grp(4)][t(32)][v4(64)] u32, 4 packed u8 counters each = 32 KB
    __shared__ uint32_t s_cnt32[4 * NVT * 64];
    __shared__ int      s_type[NN];
    __shared__ float    s_tbl[HS];

    const int tid = threadIdx.x;

    if (blockIdx.x >= BB) {
        // ================= tables block =================
        const int t = blockIdx.x - BB;       // 0..31 (type = K index)
        if (tid < HS) {
            float x  = Wg[tid * NVT + t] + bg[tid];
            float sg = __fdividef(1.f, 1.f + __expf(-x));
            s_tbl[tid] = sg * Wm[tid * NVT + t];
        }
        __syncthreads();

        unsigned short* B = (unsigned short*)g_Bf4;
        // exchange-free column map: h -> tile pair p=h>>2;
        // X tile (c=r/z) at 2p, Y tile (c=n/tbl) at 2p+1;
        // within-tile column = 2*(h&3) + (c&1)
        auto storeB = [&](int h, int c, float val) {
            int j = ((h >> 2) << 4) | ((c >> 1) << 3) | ((h & 3) << 1) | (c & 1);
            int nt = j >> 3, nin = j & 7;
            int k = t >> 4, kk = t & 15;
            int tig = (kk & 7) >> 1, half = kk & 1, reg = kk >> 3;
            int lane = nin * 4 + tig;
            int base = ((nt * 32 + lane) * 8) + k * 4 + reg * 2 + half;
            B[base] = __half_as_ushort(__float2half_rn(val));
        };

        for (int g = tid; g < G3; g += 256) {
            const float2* w2 = (const float2*)(W_hh + g * HS);
            const float2* t2 = (const float2*)s_tbl;
            float a0 = 0.f, a1 = 0.f;
            #pragma unroll 8
            for (int i = 0; i < 64; i += 2) {
                float2 w0 = w2[i], w1 = w2[i + 1];
                float2 x0 = t2[i], x1 = t2[i + 1];
                a0 += w0.x * x0.x + w0.y * x0.y;
                a1 += w1.x * x1.x + w1.y * x1.y;
            }
            float acc = a0 + a1;
            storeB(g & 127, g >> 7, acc);        // c: 0=r 1=z 2=n
            // gi packed: [h][t] {r,z,n,bhn}
            __half* GI = (__half*)g_gi4;
            int c = g >> 7, h = g & 127;
            float val = W_ih[g * NVT + t] + b_ih[g] + ((g < 256) ? b_hh[g] : 0.f);
            GI[(h * 32 + t) * 4 + c] = __float2half_rn(val);
        }
        if (tid < HS) {
            storeB(tid, 3, s_tbl[tid]);          // tbl columns
            __half* GI = (__half*)g_gi4;
            GI[(tid * 32 + t) * 4 + 3] = __float2half_rn(b_hh[256 + tid]);
        }
        return;
    }

    // ================= histogram block (packed-byte counters) =================
    const int b = blockIdx.x;
    s_type[tid] = node_types[b * NN + tid];
    for (int i = tid; i < 4 * NVT * 64; i += 256) s_cnt32[i] = 0;
    __syncthreads();

    {
        const int vg    = tid & 63;      // which v-quad (v = 4*vg .. 4*vg+3)
        const int ug    = tid >> 6;      // u-group 0..3 (private partials)
        const int ubase = ug * 64;
        const int4* arow =
            (const int4*)(adj + ((size_t)b * NN + ubase) * NN) + vg;
        uint32_t* cbase = s_cnt32 + ug * (NVT * 64) + vg;

        #pragma unroll 1
        for (int u = 0; u < 64; u += 4) {
            int4 a0 = __ldg(arow + (u + 0) * 64);
            int4 a1 = __ldg(arow + (u + 1) * 64);
            int4 a2 = __ldg(arow + (u + 2) * 64);
            int4 a3 = __ldg(arow + (u + 3) * 64);
            int t0 = s_type[ubase + u + 0];
            int t1 = s_type[ubase + u + 1];
            int t2 = s_type[ubase + u + 2];
            int t3 = s_type[ubase + u + 3];
            uint32_t p0 = (uint32_t)a0.x | ((uint32_t)a0.y << 8) |
                          ((uint32_t)a0.z << 16) | ((uint32_t)a0.w << 24);
            uint32_t p1 = (uint32_t)a1.x | ((uint32_t)a1.y << 8) |
                          ((uint32_t)a1.z << 16) | ((uint32_t)a1.w << 24);
            uint32_t p2 = (uint32_t)a2.x | ((uint32_t)a2.y << 8) |
                          ((uint32_t)a2.z << 16) | ((uint32_t)a2.w << 24);
            uint32_t p3 = (uint32_t)a3.x | ((uint32_t)a3.y << 8) |
                          ((uint32_t)a3.z << 16) | ((uint32_t)a3.w << 24);
            cbase[t0 * 64] += p0;     // 4 byte-counters per RMW
            cbase[t1 * 64] += p1;
            cbase[t2 * 64] += p2;
            cbase[t3 * 64] += p3;
        }
    }
    __syncthreads();

    // reduce the 4 u-group partials in place (bytes can't overflow: <=255 total)
    for (int i = tid; i < NVT * 64; i += 256)
        s_cnt32[i] = s_cnt32[i] + s_cnt32[NVT * 64 + i] +
                     s_cnt32[2 * NVT * 64 + i] + s_cnt32[3 * NVT * 64 + i];
    __syncthreads();

    // write A fragments: counts (0..255) are exact in fp16
    uint32_t* dst = (uint32_t*)g_Af4 + (size_t)b * 4096;
    for (int lin = tid; lin < 4096; lin += 256) {
        int reg  = lin & 3;
        int lane = (lin >> 2) & 31;
        int k    = (lin >> 7) & 1;
        int mt   = lin >> 8;
        int g    = lane >> 2, tig = lane & 3;
        int v    = mt * 16 + (reg & 1) * 8 + g;
        int t0   = k * 16 + (reg >> 1) * 8 + tig * 2;
        int sh   = (v & 3) * 8;
        uint32_t c0 = (s_cnt32[t0 * 64 + (v >> 2)] >> sh) & 255u;
        uint32_t c1 = (s_cnt32[(t0 + 1) * 64 + (v >> 2)] >> sh) & 255u;
        uint32_t u0 = (uint32_t)__half_as_ushort(__float2half_rn((float)c0));
        uint32_t u1 = (uint32_t)__half_as_ushort(__float2half_rn((float)c1));
        dst[lin] = u0 | (u1 << 16);
    }
}

// ---------- main kernel: 512 thr, 2 batches/CTA, exchange-free + B prefetch -
// smem: sB 32K + gi4 32K + spart 8K + phg 1K = 73 KB -> 2 CTAs/SM
#define SMEM_DYN (32768 + 32768 + 8192 + 1024)

__global__ __launch_bounds__(512, 2)
void dvae_main_kernel(const int* __restrict__ node_types,
                      const float* __restrict__ W1, const float* __restrict__ b1,
                      const float* __restrict__ W2, const float* __restrict__ b2,
                      float* __restrict__ out) {
    extern __shared__ char smem[];
    uint4*  sB4   = (uint4*)smem;                       // [64][32] uint4
    __half* gi4   = (__half*)(smem + 32768);            // [128][32][4]
    float*  spart = (float*)(smem + 32768 + 32768);     // [2][8][128]
    float*  phg   = (float*)(smem + 32768 + 32768 + 8192); // [2][128]

    const int tid  = threadIdx.x;
    const int wg   = tid >> 8;          // 0/1 -> which batch
    const int wid8 = (tid >> 5) & 7;    // warp within group
    const int lane = tid & 31;
    const int b    = blockIdx.x * 2 + wg;

    // ---- stage B frags + gi4 (uint4 copies, all 512 threads) ----
    for (int i = tid; i < 2048; i += 512) sB4[i] = g_Bf4[i];
    {
        uint4* d2 = (uint4*)gi4;
        for (int i = tid; i < 2048; i += 512) d2[i] = g_gi4[i];
    }
    __syncthreads();

    // ---- A fragments: 2 m-tiles per warp, 2 k-steps ----
    uint4 areg[2][2];
    #pragma unroll
    for (int mt2 = 0; mt2 < 2; mt2++)
        #pragma unroll
        for (int k = 0; k < 2; k++)
            areg[mt2][k] = g_Af4[(size_t)b * 1024 +
                                 (((wid8 * 2 + mt2) * 2 + k) * 32 + lane)];

    const int g   = lane >> 2;
    const int tig = lane & 3;

    // each thread covers v rows: (mt, half) -> v = (wid8*2+mt)*16 + g + half*8
    int  tvv[2][2];
    bool excl[2][2];
    #pragma unroll
    for (int mt = 0; mt < 2; mt++)
        #pragma unroll
        for (int hf = 0; hf < 2; hf++) {
            int v = (wid8 * 2 + mt) * 16 + g + hf * 8;
            tvv[mt][hf]  = node_types[b * NN + v];
            excl[mt][hf] = (v == 0) || (v == NN - 1);
        }

    float* spart_w = spart + (wg * 8 + wid8) * 128;

    // ---- GEMM + exchange-free epilogue, software-pipelined B loads ----
    uint4 bbX = sB4[lane];          // p = 0 tiles
    uint4 bbY = sB4[32 + lane];
    #pragma unroll 2
    for (int p = 0; p < 32; p++) {
        float ccX[2][4] = {{0.f,0.f,0.f,0.f},{0.f,0.f,0.f,0.f}};
        float ccY[2][4] = {{0.f,0.f,0.f,0.f},{0.f,0.f,0.f,0.f}};
        mma_fp16(ccX[0], (const uint32_t*)&areg[0][0], bbX.x, bbX.y);
        mma_fp16(ccX[1], (const uint32_t*)&areg[1][0], bbX.x, bbX.y);
        mma_fp16(ccY[0], (const uint32_t*)&areg[0][0], bbY.x, bbY.y);
        mma_fp16(ccY[1], (const uint32_t*)&areg[1][0], bbY.x, bbY.y);
        mma_fp16(ccX[0], (const uint32_t*)&areg[0][1], bbX.z, bbX.w);
        mma_fp16(ccX[1], (const uint32_t*)&areg[1][1], bbX.z, bbX.w);
        mma_fp16(ccY[0], (const uint32_t*)&areg[0][1], bbY.z, bbY.w);
        mma_fp16(ccY[1], (const uint32_t*)&areg[1][1], bbY.z, bbY.w);

        // prefetch next iteration's B tiles (wrapped; last load is harmless)
        const int pn = (p + 1) & 31;
        uint4 nbX = sB4[(2 * pn)     * 32 + lane];
        uint4 nbY = sB4[(2 * pn + 1) * 32 + lane];

        const int h = p * 4 + tig;     // this thread's h for the whole pair
        float acc = 0.f;
        #pragma unroll
        for (int mt = 0; mt < 2; mt++) {
            #pragma unroll
            for (int hf = 0; hf < 2; hf++) {
                // rows: c[0],c[1] = row g ; c[2],c[3] = row g+8
                float rin  = ccX[mt][hf * 2 + 0];
                float zin  = ccX[mt][hf * 2 + 1];
                float nin  = ccY[mt][hf * 2 + 0];
                float hpre = ccY[mt][hf * 2 + 1];
                uint2 gv = *(const uint2*)(gi4 + ((h * 32 + tvv[mt][hf]) << 2));
                float2 f_rz = __half22float2(*(const __half2*)&gv.x);
                float2 f_nb = __half22float2(*(const __half2*)&gv.y);
                float r  = sigmoid_fast(f_rz.x + rin);
                float z  = sigmoid_fast(f_rz.y + zin);
                float nn = tanh_fast(f_nb.x + r * (nin + f_nb.y));
                float Hv = (1.f - z) * nn + z * hpre;
                if (!excl[mt][hf]) acc += Hv;
            }
        }
        // reduce over the 8 lanes sharing this h (g = 0..7)
        acc += __shfl_xor_sync(0xffffffffu, acc, 4);
        acc += __shfl_xor_sync(0xffffffffu, acc, 8);
        acc += __shfl_xor_sync(0xffffffffu, acc, 16);
        if (lane < 4)
            spart_w[p * 4 + lane] = acc;     // h = p*4 + tig, lane==tig

        bbX = nbX;
        bbY = nbY;
    }
    __syncthreads();

    // ---- reduce partials, heads (per warp-group / batch) ----
    const int wg_tid = tid & 255;
    if (wg_tid < HS) {
        const float* sp = spart + wg * 8 * 128;
        float s = 0.f;
        #pragma unroll
        for (int w = 0; w < 8; w++) s += sp[w * 128 + wg_tid];
        phg[wg * 128 + wg_tid] = s;
    }
    __syncthreads();

    if (wg_tid < 2 * NZ) {
        const int j = wg_tid & (NZ - 1);
        const float* W  = (wg_tid < NZ) ? W1 : W2;
        const float* bv = (wg_tid < NZ) ? b1 : b2;
        const float* hgp = phg + wg * 128;
        float a0 = bv[j], a1 = 0.f, a2 = 0.f, a3 = 0.f;
        #pragma unroll
        for (int h = 0; h < HS; h += 4) {
            a0 += hgp[h + 0] * W[j * HS + h + 0];
            a1 += hgp[h + 1] * W[j * HS + h + 1];
            a2 += hgp[h + 2] * W[j * HS + h + 2];
            a3 += hgp[h + 3] * W[j * HS + h + 3];
        }
        out[((wg_tid < NZ) ? 0 : BB * NZ) + b * NZ + j] = (a0 + a1) + (a2 + a3);
    }
}

// ---------- launch ----------
extern "C" void kernel_launch(void* const* d_in, const int* in_sizes, int n_in,
                              void* d_out, int out_size) {
    const int*   node_types = (const int*)  d_in[0];
    const int*   adj        = (const int*)  d_in[1];
    const float* W_ih       = (const float*)d_in[2];
    const float* W_hh       = (const float*)d_in[3];
    const float* b_ih       = (const float*)d_in[4];
    const float* b_hh       = (const float*)d_in[5];
    const float* Wg         = (const float*)d_in[6];
    const float* bg         = (const float*)d_in[7];
    const float* Wm         = (const float*)d_in[8];
    const float* W1         = (const float*)d_in[9];
    const float* b1         = (const float*)d_in[10];
    const float* W2         = (const float*)d_in[11];
    const float* b2         = (const float*)d_in[12];
    float* out = (float*)d_out;

    cudaFuncSetAttribute(dvae_main_kernel,
                         cudaFuncAttributeMaxDynamicSharedMemorySize, SMEM_DYN);

    dvae_hist_tables_kernel<<<BB + NVT, 256>>>(node_types, adj,
                                               W_ih, W_hh, b_ih, b_hh,
                                               Wg, bg, Wm);
    dvae_main_kernel<<<BB / 2, 512, SMEM_DYN>>>(node_types,
                                                W1, b1, W2, b2, out);
}

// round 17
// speedup vs baseline: 1.1451x; 1.1451x over previous
#include <cuda_runtime.h>
#include <cuda_fp16.h>
#include <cstdint>

#define BB   512
#define NN   256
#define NVT  32
#define HS   128
#define G3   384
#define NZ   64

// ---------- device globals (no allocation allowed) ----------
// B fragments (fp16): [tile(64)][lane(32)] x uint4 = 32 KB
// tile 2p = X (r,z of h in [4p,4p+4)), tile 2p+1 = Y (n,tbl)
__device__ uint4 g_Bf4[2048];
// gi packed: [h(128)][t(32)] x 4 fp16 {gi_r, gi_z, gi_n, bhn_h} = 32 KB
__device__ uint4 g_gi4[2048];
// A fragments per batch (fp16): [mt(16)][k(2)][lane(32)][reg(4)] = 16 KB/batch
__device__ uint4 g_Af4[(size_t)BB * 1024];

__device__ __forceinline__ float tanh_fast(float x) {
    float y;
    asm("tanh.approx.f32 %0, %1;" : "=f"(y) : "f"(x));
    return y;
}
__device__ __forceinline__ float sigmoid_fast(float x) {
    return fmaf(tanh_fast(0.5f * x), 0.5f, 0.5f);
}
__device__ __forceinline__ void mma_fp16(float* c, const uint32_t* a,
                                         uint32_t b0, uint32_t b1) {
    asm volatile(
        "mma.sync.aligned.m16n8k16.row.col.f32.f16.f16.f32 "
        "{%0,%1,%2,%3}, {%4,%5,%6,%7}, {%8,%9}, {%0,%1,%2,%3};"
        : "+f"(c[0]), "+f"(c[1]), "+f"(c[2]), "+f"(c[3])
        : "r"(a[0]), "r"(a[1]), "r"(a[2]), "r"(a[3]), "r"(b0), "r"(b1));
}

// ---------- fused kernel: blocks [0,512) histogram, [512,544) tables --------
__global__ __launch_bounds__(256, 5)
void dvae_hist_tables_kernel(const int* __restrict__ node_types,
                             const int* __restrict__ adj,
                             const float* __restrict__ W_ih,
                             const float* __restrict__ W_hh,
                             const float* __restrict__ b_ih,
                             const float* __restrict__ b_hh,
                             const float* __restrict__ Wg,
                             const float* __restrict__ bg,
                             const float* __restrict__ Wm) {
    // [grp(4)][t(32)][v4(64)] u32, 4 packed u8 counters each = 32 KB
    __shared__ uint32_t s_cnt32[4 * NVT * 64];
    __shared__ int      s_type[NN];
    __shared__ float    s_tbl[HS];

    const int tid = threadIdx.x;

    if (blockIdx.x >= BB) {
        // ================= tables block =================
        const int t = blockIdx.x - BB;       // 0..31 (type = K index)
        if (tid < HS) {
            float x  = Wg[tid * NVT + t] + bg[tid];
            float sg = __fdividef(1.f, 1.f + __expf(-x));
            s_tbl[tid] = sg * Wm[tid * NVT + t];
        }
        __syncthreads();

        unsigned short* B = (unsigned short*)g_Bf4;
        // exchange-free column map: h -> tile pair p=h>>2;
        // X tile (c=r/z) at 2p, Y tile (c=n/tbl) at 2p+1;
        // within-tile column = 2*(h&3) + (c&1)
        auto storeB = [&](int h, int c, float val) {
            int j = ((h >> 2) << 4) | ((c >> 1) << 3) | ((h & 3) << 1) | (c & 1);
            int nt = j >> 3, nin = j & 7;
            int k = t >> 4, kk = t & 15;
            int tig = (kk & 7) >> 1, half = kk & 1, reg = kk >> 3;
            int lane = nin * 4 + tig;
            int base = ((nt * 32 + lane) * 8) + k * 4 + reg * 2 + half;
            B[base] = __half_as_ushort(__float2half_rn(val));
        };

        for (int g = tid; g < G3; g += 256) {
            const float2* w2 = (const float2*)(W_hh + g * HS);
            const float2* t2 = (const float2*)s_tbl;
            float a0 = 0.f, a1 = 0.f;
            #pragma unroll 8
            for (int i = 0; i < 64; i += 2) {
                float2 w0 = w2[i], w1 = w2[i + 1];
                float2 x0 = t2[i], x1 = t2[i + 1];
                a0 += w0.x * x0.x + w0.y * x0.y;
                a1 += w1.x * x1.x + w1.y * x1.y;
            }
            float acc = a0 + a1;
            storeB(g & 127, g >> 7, acc);        // c: 0=r 1=z 2=n
            // gi packed: [h][t] {r,z,n,bhn}
            __half* GI = (__half*)g_gi4;
            int c = g >> 7, h = g & 127;
            float val = W_ih[g * NVT + t] + b_ih[g] + ((g < 256) ? b_hh[g] : 0.f);
            GI[(h * 32 + t) * 4 + c] = __float2half_rn(val);
        }
        if (tid < HS) {
            storeB(tid, 3, s_tbl[tid]);          // tbl columns
            __half* GI = (__half*)g_gi4;
            GI[(tid * 32 + t) * 4 + 3] = __float2half_rn(b_hh[256 + tid]);
        }
        return;
    }

    // ================= histogram block (packed-byte counters) =================
    const int b = blockIdx.x;
    s_type[tid] = node_types[b * NN + tid];
    for (int i = tid; i < 4 * NVT * 64; i += 256) s_cnt32[i] = 0;
    __syncthreads();

    {
        const int vg    = tid & 63;      // which v-quad (v = 4*vg .. 4*vg+3)
        const int ug    = tid >> 6;      // u-group 0..3 (private partials)
        const int ubase = ug * 64;
        const int4* arow =
            (const int4*)(adj + ((size_t)b * NN + ubase) * NN) + vg;
        uint32_t* cbase = s_cnt32 + ug * (NVT * 64) + vg;

        #pragma unroll 1
        for (int u = 0; u < 64; u += 4) {
            int4 a0 = __ldg(arow + (u + 0) * 64);
            int4 a1 = __ldg(arow + (u + 1) * 64);
            int4 a2 = __ldg(arow + (u + 2) * 64);
            int4 a3 = __ldg(arow + (u + 3) * 64);
            int t0 = s_type[ubase + u + 0];
            int t1 = s_type[ubase + u + 1];
            int t2 = s_type[ubase + u + 2];
            int t3 = s_type[ubase + u + 3];
            uint32_t p0 = (uint32_t)a0.x | ((uint32_t)a0.y << 8) |
                          ((uint32_t)a0.z << 16) | ((uint32_t)a0.w << 24);
            uint32_t p1 = (uint32_t)a1.x | ((uint32_t)a1.y << 8) |
                          ((uint32_t)a1.z << 16) | ((uint32_t)a1.w << 24);
            uint32_t p2 = (uint32_t)a2.x | ((uint32_t)a2.y << 8) |
                          ((uint32_t)a2.z << 16) | ((uint32_t)a2.w << 24);
            uint32_t p3 = (uint32_t)a3.x | ((uint32_t)a3.y << 8) |
                          ((uint32_t)a3.z << 16) | ((uint32_t)a3.w << 24);
            cbase[t0 * 64] += p0;     // 4 byte-counters per RMW
            cbase[t1 * 64] += p1;
            cbase[t2 * 64] += p2;
            cbase[t3 * 64] += p3;
        }
    }
    __syncthreads();

    // reduce the 4 u-group partials in place (bytes can't overflow: <=255 total)
    for (int i = tid; i < NVT * 64; i += 256)
        s_cnt32[i] = s_cnt32[i] + s_cnt32[NVT * 64 + i] +
                     s_cnt32[2 * NVT * 64 + i] + s_cnt32[3 * NVT * 64 + i];
    __syncthreads();

    // write A fragments: counts (0..255) are exact in fp16
    uint32_t* dst = (uint32_t*)g_Af4 + (size_t)b * 4096;
    for (int lin = tid; lin < 4096; lin += 256) {
        int reg  = lin & 3;
        int lane = (lin >> 2) & 31;
        int k    = (lin >> 7) & 1;
        int mt   = lin >> 8;
        int g    = lane >> 2, tig = lane & 3;
        int v    = mt * 16 + (reg & 1) * 8 + g;
        int t0   = k * 16 + (reg >> 1) * 8 + tig * 2;
        int sh   = (v & 3) * 8;
        uint32_t c0 = (s_cnt32[t0 * 64 + (v >> 2)] >> sh) & 255u;
        uint32_t c1 = (s_cnt32[(t0 + 1) * 64 + (v >> 2)] >> sh) & 255u;
        uint32_t u0 = (uint32_t)__half_as_ushort(__float2half_rn((float)c0));
        uint32_t u1 = (uint32_t)__half_as_ushort(__float2half_rn((float)c1));
        dst[lin] = u0 | (u1 << 16);
    }
}

// ---------- main kernel: 512 thr, 2 batches/CTA, exchange-free, 1-shfl tail -
// smem: sB 32K + gi4 32K + spart 32K + phg 1K = 97 KB -> 2 CTAs/SM
#define SMEM_DYN (32768 + 32768 + 32768 + 1024)

__global__ __launch_bounds__(512, 2)
void dvae_main_kernel(const int* __restrict__ node_types,
                      const float* __restrict__ W1, const float* __restrict__ b1,
                      const float* __restrict__ W2, const float* __restrict__ b2,
                      float* __restrict__ out) {
    extern __shared__ char smem[];
    uint4*  sB4   = (uint4*)smem;                       // [64][32] uint4
    __half* gi4   = (__half*)(smem + 32768);            // [128][32][4]
    float*  spart = (float*)(smem + 32768 + 32768);     // [2][8][128][4]
    float*  phg   = (float*)(smem + 32768 + 32768 + 32768); // [2][128]

    const int tid  = threadIdx.x;
    const int wg   = tid >> 8;          // 0/1 -> which batch
    const int wid8 = (tid >> 5) & 7;    // warp within group
    const int lane = tid & 31;
    const int b    = blockIdx.x * 2 + wg;

    // ---- stage B frags + gi4 (uint4 copies, all 512 threads) ----
    for (int i = tid; i < 2048; i += 512) sB4[i] = g_Bf4[i];
    {
        uint4* d2 = (uint4*)gi4;
        for (int i = tid; i < 2048; i += 512) d2[i] = g_gi4[i];
    }
    __syncthreads();

    // ---- A fragments: 2 m-tiles per warp, 2 k-steps ----
    uint4 areg[2][2];
    #pragma unroll
    for (int mt2 = 0; mt2 < 2; mt2++)
        #pragma unroll
        for (int k = 0; k < 2; k++)
            areg[mt2][k] = g_Af4[(size_t)b * 1024 +
                                 (((wid8 * 2 + mt2) * 2 + k) * 32 + lane)];

    const int g   = lane >> 2;
    const int tig = lane & 3;

    // each thread covers v rows: (mt, half) -> v = (wid8*2+mt)*16 + g + half*8
    int  tvv[2][2];
    bool excl[2][2];
    #pragma unroll
    for (int mt = 0; mt < 2; mt++)
        #pragma unroll
        for (int hf = 0; hf < 2; hf++) {
            int v = (wid8 * 2 + mt) * 16 + g + hf * 8;
            tvv[mt][hf]  = node_types[b * NN + v];
            excl[mt][hf] = (v == 0) || (v == NN - 1);
        }

    // this warp's spart slice: [128 h][4 slots]
    float* spart_w = spart + (wg * 8 + wid8) * 512;
    const bool store_lane = ((lane & 4) == 0);   // g even
    const int  slot = lane >> 3;                 // g >> 1

    // ---- GEMM + exchange-free epilogue over 32 tile-pairs ----
    #pragma unroll 1
    for (int p = 0; p < 32; p++) {
        uint4 bbX = sB4[(2 * p)     * 32 + lane];   // (r,z)  columns
        uint4 bbY = sB4[(2 * p + 1) * 32 + lane];   // (n,tbl) columns
        float ccX[2][4] = {{0.f,0.f,0.f,0.f},{0.f,0.f,0.f,0.f}};
        float ccY[2][4] = {{0.f,0.f,0.f,0.f},{0.f,0.f,0.f,0.f}};
        mma_fp16(ccX[0], (const uint32_t*)&areg[0][0], bbX.x, bbX.y);
        mma_fp16(ccX[1], (const uint32_t*)&areg[1][0], bbX.x, bbX.y);
        mma_fp16(ccY[0], (const uint32_t*)&areg[0][0], bbY.x, bbY.y);
        mma_fp16(ccY[1], (const uint32_t*)&areg[1][0], bbY.x, bbY.y);
        mma_fp16(ccX[0], (const uint32_t*)&areg[0][1], bbX.z, bbX.w);
        mma_fp16(ccX[1], (const uint32_t*)&areg[1][1], bbX.z, bbX.w);
        mma_fp16(ccY[0], (const uint32_t*)&areg[0][1], bbY.z, bbY.w);
        mma_fp16(ccY[1], (const uint32_t*)&areg[1][1], bbY.z, bbY.w);

        const int h = p * 4 + tig;     // this thread's h for the whole pair
        float acc0 = 0.f, acc1 = 0.f;  // independent chains per mt
        #pragma unroll
        for (int mt = 0; mt < 2; mt++) {
            #pragma unroll
            for (int hf = 0; hf < 2; hf++) {
                // rows: c[0],c[1] = row g ; c[2],c[3] = row g+8
                float rin  = ccX[mt][hf * 2 + 0];
                float zin  = ccX[mt][hf * 2 + 1];
                float nin  = ccY[mt][hf * 2 + 0];
                float hpre = ccY[mt][hf * 2 + 1];
                uint2 gv = *(const uint2*)(gi4 + ((h * 32 + tvv[mt][hf]) << 2));
                float2 f_rz = __half22float2(*(const __half2*)&gv.x);
                float2 f_nb = __half22float2(*(const __half2*)&gv.y);
                float r  = sigmoid_fast(f_rz.x + rin);
                float z  = sigmoid_fast(f_rz.y + zin);
                float nn = tanh_fast(f_nb.x + r * (nin + f_nb.y));
                float Hv = (1.f - z) * nn + z * hpre;
                if (!excl[mt][hf]) { if (mt) acc1 += Hv; else acc0 += Hv; }
            }
        }
        float acc = acc0 + acc1;
        // partial reduce: one shfl (pairs g with g^1); 4 partials per h remain
        acc += __shfl_xor_sync(0xffffffffu, acc, 4);
        if (store_lane)
            spart_w[h * 4 + slot] = acc;   // indices 16p+tig*4+slot: no conflicts
    }
    __syncthreads();

    // ---- reduce partials, heads (per warp-group / batch) ----
    const int wg_tid = tid & 255;
    if (wg_tid < HS) {
        const float4* sp = (const float4*)(spart + wg * 8 * 512);
        float s = 0.f;
        #pragma unroll
        for (int w = 0; w < 8; w++) {
            float4 v = sp[w * 128 + wg_tid];
            s += (v.x + v.y) + (v.z + v.w);
        }
        phg[wg * 128 + wg_tid] = s;
    }
    __syncthreads();

    if (wg_tid < 2 * NZ) {
        const int j = wg_tid & (NZ - 1);
        const float* W  = (wg_tid < NZ) ? W1 : W2;
        const float* bv = (wg_tid < NZ) ? b1 : b2;
        const float* hgp = phg + wg * 128;
        float a0 = bv[j], a1 = 0.f, a2 = 0.f, a3 = 0.f;
        #pragma unroll
        for (int h = 0; h < HS; h += 4) {
            a0 += hgp[h + 0] * W[j * HS + h + 0];
            a1 += hgp[h + 1] * W[j * HS + h + 1];
            a2 += hgp[h + 2] * W[j * HS + h + 2];
            a3 += hgp[h + 3] * W[j * HS + h + 3];
        }
        out[((wg_tid < NZ) ? 0 : BB * NZ) + b * NZ + j] = (a0 + a1) + (a2 + a3);
    }
}

// ---------- launch ----------
extern "C" void kernel_launch(void* const* d_in, const int* in_sizes, int n_in,
                              void* d_out, int out_size) {
    const int*   node_types = (const int*)  d_in[0];
    const int*   adj        = (const int*)  d_in[1];
    const float* W_ih       = (const float*)d_in[2];
    const float* W_hh       = (const float*)d_in[3];
    const float* b_ih       = (const float*)d_in[4];
    const float* b_hh       = (const float*)d_in[5];
    const float* Wg         = (const float*)d_in[6];
    const float* bg         = (const float*)d_in[7];
    const float* Wm         = (const float*)d_in[8];
    const float* W1         = (const float*)d_in[9];
    const float* b1         = (const float*)d_in[10];
    const float* W2         = (const float*)d_in[11];
    const float* b2         = (const float*)d_in[12];
    float* out = (float*)d_out;

    cudaFuncSetAttribute(dvae_main_kernel,
                         cudaFuncAttributeMaxDynamicSharedMemorySize, SMEM_DYN);

    dvae_hist_tables_kernel<<<BB + NVT, 256>>>(node_types, adj,
                                               W_ih, W_hh, b_ih, b_hh,
                                               Wg, bg, Wm);
    dvae_main_kernel<<<BB / 2, 512, SMEM_DYN>>>(node_types,
                                                W1, b1, W2, b2, out);
}